// round 9
// baseline (speedup 1.0000x reference)
#include <cuda_runtime.h>

#define TT    128
#define HORZ  24
#define LOG2E 1.44269504f

typedef unsigned long long u64;

// ---------------- global scratch (sanctioned __device__ arrays) ----------------
__device__ float g_H [4096 * TT * 64];   // H[b][t][j]  (h_t at row t)  134 MB
__device__ float g_Hp[4096 * TT * 32];   // Hp[b][t][a]                 67 MB
__device__ float g_d0[4096 * 64];        // d0[b][j]                     1 MB

// ---------------- device helpers ----------------
__device__ __forceinline__ void fma2(u64 &acc, u64 w, u64 h){
    asm("fma.rn.f32x2 %0, %1, %2, %0;" : "+l"(acc) : "l"(w), "l"(h));
}
__device__ __forceinline__ float hsum2(u64 a){
    return __uint_as_float((unsigned)a) + __uint_as_float((unsigned)(a >> 32));
}
__device__ __forceinline__ float ex2f(float x){ float y; asm("ex2.approx.f32 %0, %1;" : "=f"(y) : "f"(x)); return y; }
__device__ __forceinline__ float rcpf(float x){ float y; asm("rcp.approx.f32 %0, %1;" : "=f"(y) : "f"(x)); return y; }
__device__ __forceinline__ float sigm(float x){ return rcpf(1.0f + ex2f(-LOG2E * x)); }
__device__ __forceinline__ float tanh_acc(float x){
    float xx = fminf(15.0f, fmaxf(-15.0f, x));
    float e  = ex2f(2.0f * LOG2E * xx);
    return (e - 1.0f) * rcpf(e + 1.0f);
}
__device__ __forceinline__ float tanh_fast(float x){
    float y; asm("tanh.approx.f32 %0, %1;" : "=f"(y) : "f"(x)); return y;
}

// ================= KERNEL 1: R6-proven encoder (per-b CTA) -> global ==========
#define K1_H     0                       // 129 x 64 (row 0 = h_{-1} = 0)
#define K1_HP    (K1_H + 129*64)         // 128 x 33
#define K1_XS    (K1_HP + 128*33)        // 128
#define K1_DBUF  (K1_XS + 128)           // 64 used
#define K1_PR    (K1_DBUF + 128)         // 128
#define K1_PZ    (K1_PR + 128)           // 128
#define K1_PN    (K1_PZ + 128)           // 128
#define K1_FLOATS (K1_PN + 128)
#define K1_BYTES  (K1_FLOATS * 4)

extern "C" __global__ void __launch_bounds__(128, 4)
darnn_enc_pb(const float* __restrict__ x,
             const float* __restrict__ W_ih_e, const float* __restrict__ W_hh_e,
             const float* __restrict__ b_ih_e, const float* __restrict__ b_hh_e,
             const float* __restrict__ W_init, const float* __restrict__ b_init,
             const float* __restrict__ U_d)
{
    extern __shared__ __align__(16) float sm[];
    float* H    = sm + K1_H;
    float* Hp   = sm + K1_HP;
    float* xs   = sm + K1_XS;
    float* dbuf = sm + K1_DBUF;
    float* pR   = sm + K1_PR;
    float* pZ   = sm + K1_PZ;
    float* pN   = sm + K1_PN;

    const int tid  = threadIdx.x;
    const int b    = blockIdx.x;
    const int lane = tid & 31;
    const int warp = tid >> 5;
    const int j    = ((warp >> 1) << 5) + lane;   // output unit 0..63
    const int kh   = warp & 1;                    // k-half
    const bool fin = (kh == 0);

    // ---- encoder GRU weights: 3 half-rows (k-split) — verbatim R6
    u64 wr[16], wz[16], wn[16];
    {
        const u64* Wr = (const u64*)(W_hh_e + (j)       * 64 + kh * 32);
        const u64* Wz = (const u64*)(W_hh_e + (64 + j)  * 64 + kh * 32);
        const u64* Wn = (const u64*)(W_hh_e + (128 + j) * 64 + kh * 32);
        #pragma unroll
        for (int k = 0; k < 16; k++){ wr[k] = Wr[k]; wz[k] = Wz[k]; wn[k] = Wn[k]; }
    }
    const float wih_r = W_ih_e[j], wih_z = W_ih_e[64 + j], wih_n = W_ih_e[128 + j];
    const float br  = b_ih_e[j]       + b_hh_e[j];
    const float bz  = b_ih_e[64 + j]  + b_hh_e[64 + j];
    const float bin = b_ih_e[128 + j];
    const float bhn = b_hh_e[128 + j];

    xs[tid] = x[(size_t)b * TT + tid];
    if (tid < 64) H[tid] = 0.0f;
    __syncthreads();

    // ---- encoder: 128 GRU steps, 4-warp k-split (verbatim R6)
    float hcur = 0.0f;
    for (int t = 0; t < TT; t++){
        const float* hrow = H + t * 64 + kh * 32;
        u64 ar = 0ULL, az = 0ULL, an = 0ULL;
        #pragma unroll
        for (int k = 0; k < 8; k++){
            ulonglong2 h2 = *(const ulonglong2*)(hrow + k * 4);
            fma2(ar, wr[2*k], h2.x); fma2(ar, wr[2*k+1], h2.y);
            fma2(az, wz[2*k], h2.x); fma2(az, wz[2*k+1], h2.y);
            fma2(an, wn[2*k], h2.x); fma2(an, wn[2*k+1], h2.y);
        }
        pR[kh * 64 + j] = hsum2(ar);
        pZ[kh * 64 + j] = hsum2(az);
        pN[kh * 64 + j] = hsum2(an);
        __syncthreads();
        if (fin){
            float xt = xs[t];
            float r  = sigm(fmaf(xt, wih_r, br) + pR[j] + pR[64 + j]);
            float z  = sigm(fmaf(xt, wih_z, bz) + pZ[j] + pZ[64 + j]);
            float n  = tanh_acc(fmaf(xt, wih_n, bin) + r * (pN[j] + pN[64 + j] + bhn));
            hcur = n + z * (hcur - n);
            H[(t + 1) * 64 + j] = hcur;
        }
        __syncthreads();
    }

    // ---- H_proj pass: warp owns 32 t's, lane = a (verbatim R6)
    {
        u64 ud[32];
        const u64* U = (const u64*)(U_d + lane * 64);
        #pragma unroll
        for (int k = 0; k < 32; k++) ud[k] = U[k];
        for (int tt = 0; tt < 32; tt++){
            int t = warp * 32 + tt;
            const float* hrow = H + (t + 1) * 64;
            u64 acc = 0ULL;
            #pragma unroll
            for (int k = 0; k < 16; k++){
                ulonglong2 h2 = *(const ulonglong2*)(hrow + k * 4);
                fma2(acc, ud[2*k], h2.x); fma2(acc, ud[2*k+1], h2.y);
            }
            Hp[t * 33 + lane] = hsum2(acc);
        }
    }

    // ---- d0 = W_init . h_T + b_init (k-split, verbatim R6)
    {
        const ulonglong2* Wi = (const ulonglong2*)(W_init + j * 64 + kh * 32);
        const float* hT = H + TT * 64 + kh * 32;
        u64 acc = 0ULL;
        #pragma unroll
        for (int k = 0; k < 8; k++){
            ulonglong2 h2 = *(const ulonglong2*)(hT + k * 4);
            ulonglong2 w2 = Wi[k];
            fma2(acc, w2.x, h2.x); fma2(acc, w2.y, h2.y);
        }
        pR[kh * 64 + j] = hsum2(acc);
    }
    __syncthreads();
    if (fin) dbuf[j] = pR[j] + pR[64 + j] + b_init[j];
    __syncthreads();                                   // H, Hp, dbuf all visible

    // ---- dump to global scratch
    {
        const float4* srcH = (const float4*)(H + 64);              // rows 1..128 = h_0..h_127
        float4* dstH = (float4*)(g_H + (size_t)b * (TT * 64));
        for (int i = tid; i < TT * 64 / 4; i += 128) dstH[i] = srcH[i];
        float* dstHp = g_Hp + (size_t)b * (TT * 32);
        for (int i = tid; i < TT * 32; i += 128){
            int tt = i >> 5, a = i & 31;
            dstHp[i] = Hp[tt * 33 + a];
        }
        if (tid < 64) g_d0[(size_t)b * 64 + tid] = dbuf[tid];
    }
}

// ================= KERNEL 2: decoder (R8 structure, d0 staged) ================
#define DSM_H     0                      // 128 x 64 (h_t at row t)
#define DSM_HP    (DSM_H + 128*64)       // 128 x 33
#define DSM_DBUF  (DSM_HP + 128*33)      // 2 x 64
#define DSM_PR    (DSM_DBUF + 128)       // 128
#define DSM_PZ    (DSM_PR + 128)         // 128
#define DSM_PN    (DSM_PZ + 128)         // 128
#define DSM_DPV   (DSM_PN + 128)         // 32
#define DSM_EBUF  (DSM_DPV + 32)         // 128
#define DSM_VD    (DSM_EBUF + 128)       // 32
#define DSM_RED   (DSM_VD + 32)          // 16
#define DSM_CP    (DSM_RED + 16)         // 128
#define DSM_FLOATS (DSM_CP + 128)
#define DSM_BYTES  (DSM_FLOATS * 4)

extern "C" __global__ void __launch_bounds__(128, 4)
darnn_decoder(const float* __restrict__ W_ih_d, const float* __restrict__ W_hh_d,
              const float* __restrict__ b_ih_d, const float* __restrict__ b_hh_d,
              const float* __restrict__ W_d,    const float* __restrict__ v_d,
              const float* __restrict__ W_out,  const float* __restrict__ b_out,
              const float* __restrict__ y0,
              float* __restrict__ out)
{
    extern __shared__ __align__(16) float sm[];
    float* Hs   = sm + DSM_H;
    float* Hps  = sm + DSM_HP;
    float* dbuf = sm + DSM_DBUF;
    float* pR   = sm + DSM_PR;
    float* pZ   = sm + DSM_PZ;
    float* pN   = sm + DSM_PN;
    float* dpv  = sm + DSM_DPV;
    float* ebuf = sm + DSM_EBUF;
    float* vd   = sm + DSM_VD;
    float* red  = sm + DSM_RED;
    float* cp   = sm + DSM_CP;

    const int tid  = threadIdx.x;
    const int b    = blockIdx.x;
    const int lane = tid & 31;
    const int warp = tid >> 5;
    const int j    = ((warp >> 1) << 5) + lane;
    const int kh   = warp & 1;
    const bool fin = (kh == 0);

    // ---- stage H / Hp / d0 from global scratch
    {
        const float4* gH = (const float4*)(g_H + (size_t)b * (TT * 64));
        float4* dH = (float4*)Hs;
        for (int i = tid; i < TT * 64 / 4; i += 128) dH[i] = gH[i];
        const float* gHp = g_Hp + (size_t)b * (TT * 32);
        for (int i = tid; i < TT * 32; i += 128){
            int tt = i >> 5, a = i & 31;
            Hps[tt * 33 + a] = gHp[i];
        }
        if (tid < 64) dbuf[tid] = g_d0[(size_t)b * 64 + tid];   // buffer 0
    }
    if (tid < 32) vd[tid] = v_d[tid];
    __syncthreads();

    // ---- decoder GRU weights: 3 half-rows per thread (k-split)
    u64 wr[16], wz[16], wn[16];
    {
        const u64* Wr = (const u64*)(W_hh_d + (j)       * 64 + kh * 32);
        const u64* Wz = (const u64*)(W_hh_d + (64 + j)  * 64 + kh * 32);
        const u64* Wn = (const u64*)(W_hh_d + (128 + j) * 64 + kh * 32);
        #pragma unroll
        for (int k = 0; k < 16; k++){ wr[k] = Wr[k]; wz[k] = Wz[k]; wn[k] = Wn[k]; }
    }
    const float wih_r = W_ih_d[j], wih_z = W_ih_d[64 + j], wih_n = W_ih_d[128 + j];
    const float br  = b_ih_d[j]      + b_hh_d[j];
    const float bz  = b_ih_d[64 + j] + b_hh_d[64 + j];
    const float bin = b_ih_d[128 + j];
    const float bhn = b_hh_d[128 + j];
    const float wout_d = W_out[j], wout_c = W_out[64 + j];
    const float bo = b_out[0];
    float xdec = y0[0];
    float dj = fin ? dbuf[j] : 0.0f;

    // ---- 24 decoder steps (verbatim R6/R8)
    for (int s = 0; s < HORZ; s++){
        const float* drow   = dbuf + (s & 1) * 64;
        float*       drow_n = dbuf + ((s + 1) & 1) * 64;

        {
            const float* hrow = drow + kh * 32;
            u64 ar = 0ULL, az = 0ULL, an = 0ULL;
            #pragma unroll
            for (int k = 0; k < 8; k++){
                ulonglong2 h2 = *(const ulonglong2*)(hrow + k * 4);
                fma2(ar, wr[2*k], h2.x); fma2(ar, wr[2*k+1], h2.y);
                fma2(az, wz[2*k], h2.x); fma2(az, wz[2*k+1], h2.y);
                fma2(an, wn[2*k], h2.x); fma2(an, wn[2*k+1], h2.y);
            }
            pR[kh * 64 + j] = hsum2(ar);
            pZ[kh * 64 + j] = hsum2(az);
            pN[kh * 64 + j] = hsum2(an);
        }
        __syncthreads();                                   // B1
        if (fin){
            float r  = sigm(fmaf(xdec, wih_r, br) + pR[j] + pR[64 + j]);
            float z  = sigm(fmaf(xdec, wih_z, bz) + pZ[j] + pZ[64 + j]);
            float n  = tanh_acc(fmaf(xdec, wih_n, bin) + r * (pN[j] + pN[64 + j] + bhn));
            dj = n + z * (dj - n);
            drow_n[j] = dj;
        }
        __syncthreads();                                   // B2

        // d_proj quarter-split: a = lane, k-quarter = warp
        {
            const ulonglong2* Wd = (const ulonglong2*)(W_d + lane * 64 + warp * 16);
            const float* dsrc = drow_n + warp * 16;
            u64 acc = 0ULL;
            #pragma unroll
            for (int k = 0; k < 4; k++){
                ulonglong2 d2 = *(const ulonglong2*)(dsrc + k * 4);
                ulonglong2 w2 = Wd[k];
                fma2(acc, w2.x, d2.x); fma2(acc, w2.y, d2.y);
            }
            cp[warp * 32 + lane] = hsum2(acc);
        }
        __syncthreads();                                   // B3
        if (tid < 32) dpv[tid] = (cp[tid] + cp[32 + tid]) + (cp[64 + tid] + cp[96 + tid]);
        __syncthreads();                                   // B4

        // scores: one t per thread; softmax without max (scores bounded)
        {
            const float* hpt = Hps + tid * 33;
            float sc = 0.0f;
            #pragma unroll 8
            for (int a = 0; a < 32; a++)
                sc = fmaf(vd[a], tanh_fast(dpv[a] + hpt[a]), sc);
            float e = ex2f(sc * LOG2E);
            ebuf[tid] = e;
            float esum = e;
            #pragma unroll
            for (int o = 16; o > 0; o >>= 1) esum += __shfl_xor_sync(0xffffffffu, esum, o);
            if (lane == 0) red[4 + warp] = esum;
        }
        __syncthreads();                                   // B5
        float inv = rcpf((red[4] + red[5]) + (red[6] + red[7]));

        // ctx partials: thread (jc, th) sums its 64-t range
        {
            const int jc = tid & 63, th = tid >> 6;
            const float* Hb = Hs + (th * 64) * 64;
            const float* eb = ebuf + th * 64;
            float c = 0.0f;
            #pragma unroll 8
            for (int t2 = 0; t2 < 64; t2++)
                c = fmaf(eb[t2], Hb[t2 * 64 + jc], c);
            cp[tid] = c;
        }
        __syncthreads();                                   // B6
        if (fin){
            float ctxj = (cp[j] + cp[64 + j]) * inv;
            float part = fmaf(wout_d, dj, wout_c * ctxj);
            #pragma unroll
            for (int o = 16; o > 0; o >>= 1) part += __shfl_xor_sync(0xffffffffu, part, o);
            if (lane == 0) red[8 + (warp >> 1)] = part;
        }
        __syncthreads();                                   // B7
        float val = red[8] + red[9] + bo;
        if (tid == 0) out[b * HORZ + s] = val;
        xdec = val;
    }
}

extern "C" void kernel_launch(void* const* d_in, const int* in_sizes, int n_in,
                              void* d_out, int out_size)
{
    (void)in_sizes; (void)n_in; (void)out_size;
    const float* x      = (const float*)d_in[0];
    const float* W_ih_e = (const float*)d_in[1];
    const float* W_hh_e = (const float*)d_in[2];
    const float* b_ih_e = (const float*)d_in[3];
    const float* b_hh_e = (const float*)d_in[4];
    // d_in[5..8] dead (encoder input attention == softmax over singleton axis)
    const float* W_init = (const float*)d_in[9];
    const float* b_init = (const float*)d_in[10];
    const float* W_ih_d = (const float*)d_in[11];
    const float* W_hh_d = (const float*)d_in[12];
    const float* b_ih_d = (const float*)d_in[13];
    const float* b_hh_d = (const float*)d_in[14];
    const float* W_d    = (const float*)d_in[15];
    const float* U_d    = (const float*)d_in[16];
    const float* v_d    = (const float*)d_in[17];
    const float* W_out  = (const float*)d_in[18];
    const float* b_out  = (const float*)d_in[19];
    const float* y0     = (const float*)d_in[20];
    float* out = (float*)d_out;

    cudaFuncSetAttribute(darnn_enc_pb,  cudaFuncAttributeMaxDynamicSharedMemorySize, K1_BYTES);
    cudaFuncSetAttribute(darnn_decoder, cudaFuncAttributeMaxDynamicSharedMemorySize, DSM_BYTES);

    darnn_enc_pb<<<4096, 128, K1_BYTES>>>(x, W_ih_e, W_hh_e, b_ih_e, b_hh_e,
                                          W_init, b_init, U_d);
    darnn_decoder<<<4096, 128, DSM_BYTES>>>(W_ih_d, W_hh_d, b_ih_d, b_hh_d,
                                            W_d, v_d, W_out, b_out, y0, out);
}